// round 12
// baseline (speedup 1.0000x reference)
#include <cuda_runtime.h>
#include <cuda_fp16.h>
#include <cstdint>
#include <cstddef>

// ---------------- problem constants ----------------
#define M_DIM 8192
#define N_DIM 4096
#define K_DIM 4096

// ---------------- GEMM tiling ----------------
#define BM 256
#define BN 128
// One iteration consumes 128 k-halves, stored as two 64-k sub-tiles (128B rows).
#define KSTEP 128
#define NITER (K_DIM / KSTEP)               // 32
#define STAGES 2
#define SUB_A (BM * 128)                    // 32768 bytes (A sub-tile)
#define SUB_B (BN * 128)                    // 16384 bytes (B sub-tile)
#define STAGE_HALF (SUB_A + SUB_B)          // 49152 (one 64-k sub-tile pair)
#define FULLSTAGE (2 * STAGE_HALF)          // 98304 (one 128-k stage)
#define THREADS 256
#define UNITS_A (BM * 8)                    // 2048
#define UNITS_TOT ((BM + BN) * 8)           // 3072 16B units per sub-tile
#define UPT (UNITS_TOT / THREADS)           // 12 units/thread/sub-tile (x2 halves = 24 cp.async)
#define SMEM_DYN (STAGES * FULLSTAGE + 1024)

// prep kernel split point
#define QUANT_BLOCKS 16384                  // 131072 groups / 8 per block
#define CVT_BLOCKS 32768                    // 8.39M float4 / 256

// fp16 scratch (device globals; no allocation allowed)
__device__ __half g_Xh[(size_t)M_DIM * K_DIM];
__device__ __half g_Wh[(size_t)N_DIM * K_DIM];

// ---------------- helpers ----------------
static __device__ __forceinline__ uint32_t smem_u32(const void* p) {
    uint32_t a;
    asm("{ .reg .u64 t; cvta.to.shared.u64 t, %1; cvt.u32.u64 %0, t; }" : "=r"(a) : "l"(p));
    return a;
}
static __device__ __forceinline__ uint32_t sw128(uint32_t x) { return x ^ ((x >> 3) & 0x70); }

static __device__ __forceinline__ void cp16(uint32_t s, const void* g) {
    asm volatile("cp.async.cg.shared.global [%0], [%1], 16;" :: "r"(s), "l"(g) : "memory");
}
static __device__ __forceinline__ void cp_commit() {
    asm volatile("cp.async.commit_group;" ::: "memory");
}
static __device__ __forceinline__ void cp_wait0() {
    asm volatile("cp.async.wait_group 0;" ::: "memory");
}

#define LDSM_X4(r0, r1, r2, r3, addr)                                         \
    asm volatile("ldmatrix.sync.aligned.m8n8.x4.shared.b16 {%0,%1,%2,%3}, [%4];" \
                 : "=r"(r0), "=r"(r1), "=r"(r2), "=r"(r3) : "r"(addr))

#define MMA16816(c0, c1, c2, c3, a0, a1, a2, a3, b0, b1)                      \
    asm volatile("mma.sync.aligned.m16n8k16.row.col.f32.f16.f16.f32 "         \
                 "{%0,%1,%2,%3}, {%4,%5,%6,%7}, {%8,%9}, {%0,%1,%2,%3};"      \
                 : "+f"(c0), "+f"(c1), "+f"(c2), "+f"(c3)                     \
                 : "r"(a0), "r"(a1), "r"(a2), "r"(a3), "r"(b0), "r"(b1))

// ---------------- fused prep kernel ----------------
// Blocks [0, QUANT_BLOCKS): warp-per-group int4 fake quant of weight -> g_Wh.
// Blocks [QUANT_BLOCKS, ...): x fp32 -> fp16 -> g_Xh.
__global__ void prep_kernel(const float4* __restrict__ w4, const float4* __restrict__ x4) {
    if (blockIdx.x < QUANT_BLOCKS) {
        const int warp = threadIdx.x >> 5, lane = threadIdx.x & 31;
        const size_t g = (size_t)blockIdx.x * 8 + warp;      // group id
        float4 v = w4[g * 32 + lane];
        float a = fmaxf(fmaxf(fabsf(v.x), fabsf(v.y)), fmaxf(fabsf(v.z), fabsf(v.w)));
        #pragma unroll
        for (int o = 16; o > 0; o >>= 1) a = fmaxf(a, __shfl_xor_sync(0xFFFFFFFFu, a, o));
        float scale = a / 7.0f;
        float safe = (scale > 0.0f) ? scale : 1.0f;
        float q0 = fminf(fmaxf(rintf(v.x / safe), -8.0f), 7.0f) * scale;
        float q1 = fminf(fmaxf(rintf(v.y / safe), -8.0f), 7.0f) * scale;
        float q2 = fminf(fmaxf(rintf(v.z / safe), -8.0f), 7.0f) * scale;
        float q3 = fminf(fmaxf(rintf(v.w / safe), -8.0f), 7.0f) * scale;
        __half2 h0 = __floats2half2_rn(q0, q1);
        __half2 h1 = __floats2half2_rn(q2, q3);
        uint2 u;
        u.x = *reinterpret_cast<uint32_t*>(&h0);
        u.y = *reinterpret_cast<uint32_t*>(&h1);
        *reinterpret_cast<uint2*>(g_Wh + g * 128 + lane * 4) = u;
    } else {
        const size_t i = (size_t)(blockIdx.x - QUANT_BLOCKS) * blockDim.x + threadIdx.x;
        float4 v = x4[i];
        __half2* o = reinterpret_cast<__half2*>(g_Xh);
        o[2 * i + 0] = __floats2half2_rn(v.x, v.y);
        o[2 * i + 1] = __floats2half2_rn(v.z, v.w);
    }
}

// ---------------- GEMM kernel ----------------
// 256x128 CTA tile, 128-k per iteration (2 x 64-k sub-tiles), 2-stage ring,
// ONE barrier per iteration, cp.async issue interleaved into the MMA body.
// 8 warps in 4(m) x 2(n): warp tile 64x64, register double-buffered fragments.
__global__ void __launch_bounds__(THREADS, 1)
gemm_kernel(const float* __restrict__ bias, float* __restrict__ out) {
    extern __shared__ char dsm[];
    const uint32_t tiles = (smem_u32(dsm) + 1023u) & ~1023u;

    const int tid = threadIdx.x;
    const int m0 = blockIdx.y * BM;
    const int n0 = blockIdx.x * BN;

    // ---- per-thread cp.async unit mapping (12 x 16B per sub-tile) ----
    uint32_t soff[UPT];
    uint32_t goff[UPT];                    // element offset from g_Xh / g_Wh
    #pragma unroll
    for (int i = 0; i < UPT; ++i) {
        int u = i * THREADS + tid;
        if (u < UNITS_A) {                         // A units (i = 0..7)
            int r = u >> 3, j = u & 7;
            soff[i] = sw128((uint32_t)(r * 128 + j * 16));
            goff[i] = (uint32_t)((m0 + r) * K_DIM + j * 8);
        } else {                                   // B units (i = 8..11)
            int v = u - UNITS_A;
            int r = v >> 3, j = v & 7;
            soff[i] = (uint32_t)SUB_A + sw128((uint32_t)(r * 128 + j * 16));
            goff[i] = (uint32_t)((n0 + r) * K_DIM + j * 8);
        }
    }

    // ---- warp/lane geometry: 4(m) x 2(n), warp tile 64x64 ----
    const int warp = tid >> 5, lane = tid & 31;
    const int wm = warp >> 1;
    const int wn = warp & 1;

    const int arow = wm * 64 + (lane & 15);
    const uint32_t a_base_off = (uint32_t)arow * 128;
    const uint32_t a_xor = ((uint32_t)arow & 7u) << 4;
    const uint32_t a_ku = ((uint32_t)lane >> 4) * 16;

    const int brow = wn * 64 + (lane & 15);
    const uint32_t b_base_off = (uint32_t)SUB_A + (uint32_t)brow * 128;
    const uint32_t b_xor = ((uint32_t)brow & 7u) << 4;
    const uint32_t b_ku = ((uint32_t)lane >> 4) * 16;

    float acc[4][8][4];
    #pragma unroll
    for (int i = 0; i < 4; ++i)
        #pragma unroll
        for (int j = 0; j < 8; ++j)
            #pragma unroll
            for (int k = 0; k < 4; ++k) acc[i][j][k] = 0.0f;

    // ---- prologue: load chunk 0 (both halves) into stage 0 ----
    #pragma unroll
    for (int i = 0; i < UPT; ++i) {
        const __half* base = (i < 8) ? g_Xh : g_Wh;
        cp16(tiles + soff[i], base + goff[i]);
        cp16(tiles + STAGE_HALF + soff[i], base + goff[i] + 64);
    }
    cp_commit();

    // cp.async issue schedule across the 8 kk steps: counts 2,1,2,1,2,1,2,1 = 12 units
    // (each unit issues 2 cp16: one per 64-k half)

    // ---- main loop: one barrier per 128-k iteration ----
    for (int c = 0; c < NITER; ++c) {
        cp_wait0();            // chunk c fully arrived (only committed group in flight)
        __syncthreads();       // visibility + write-after-read for the ring

        const uint32_t stg = tiles + (uint32_t)(c & 1) * FULLSTAGE;
        const uint32_t nstg = tiles + (uint32_t)((c + 1) & 1) * FULLSTAGE;
        const int issue_ok = (c + 1 < NITER);
        const uint32_t gk = (uint32_t)((c + 1) * KSTEP);

        uint32_t a[2][4][4], rb[2][4][4];

        // prefetch kk=0 fragments (sub-tile 0)
        {
            const uint32_t acol = a_ku ^ a_xor;
            const uint32_t bcol = b_ku ^ b_xor;
            #pragma unroll
            for (int mt = 0; mt < 4; ++mt)
                LDSM_X4(a[0][mt][0], a[0][mt][1], a[0][mt][2], a[0][mt][3],
                        stg + a_base_off + (uint32_t)(mt * 2048) + acol);
            #pragma unroll
            for (int ng = 0; ng < 4; ++ng)
                LDSM_X4(rb[0][ng][0], rb[0][ng][1], rb[0][ng][2], rb[0][ng][3],
                        stg + b_base_off + (uint32_t)(ng * 2048) + bcol);
        }

        #pragma unroll
        for (int kk = 0; kk < 8; ++kk) {
            const int cur = kk & 1, nxt = cur ^ 1;

            // prefetch kk+1 fragments
            if (kk < 7) {
                const int kn = kk + 1;
                const uint32_t hb = stg + (uint32_t)(kn >> 2) * STAGE_HALF;
                const uint32_t acol = ((uint32_t)((kn & 3) * 32) + a_ku) ^ a_xor;
                const uint32_t bcol = ((uint32_t)((kn & 3) * 32) + b_ku) ^ b_xor;
                #pragma unroll
                for (int mt = 0; mt < 4; ++mt)
                    LDSM_X4(a[nxt][mt][0], a[nxt][mt][1], a[nxt][mt][2], a[nxt][mt][3],
                            hb + a_base_off + (uint32_t)(mt * 2048) + acol);
                #pragma unroll
                for (int ng = 0; ng < 4; ++ng)
                    LDSM_X4(rb[nxt][ng][0], rb[nxt][ng][1], rb[nxt][ng][2], rb[nxt][ng][3],
                            hb + b_base_off + (uint32_t)(ng * 2048) + bcol);
            }

            // interleaved cp.async issue for chunk c+1 (units IDX[kk]..IDX[kk+1])
            if (issue_ok) {
                const int u0 = (12 * kk) / 8;
                const int u1 = (12 * (kk + 1)) / 8;
                #pragma unroll
                for (int i = u0; i < u1; ++i) {
                    const __half* base = (i < 8) ? g_Xh : g_Wh;
                    cp16(nstg + soff[i], base + goff[i] + gk);
                    cp16(nstg + STAGE_HALF + soff[i], base + goff[i] + gk + 64);
                }
            }

            // 32 MMAs with current fragments
            #pragma unroll
            for (int mt = 0; mt < 4; ++mt) {
                #pragma unroll
                for (int ng = 0; ng < 4; ++ng) {
                    MMA16816(acc[mt][ng * 2 + 0][0], acc[mt][ng * 2 + 0][1],
                             acc[mt][ng * 2 + 0][2], acc[mt][ng * 2 + 0][3],
                             a[cur][mt][0], a[cur][mt][1], a[cur][mt][2], a[cur][mt][3],
                             rb[cur][ng][0], rb[cur][ng][2]);
                    MMA16816(acc[mt][ng * 2 + 1][0], acc[mt][ng * 2 + 1][1],
                             acc[mt][ng * 2 + 1][2], acc[mt][ng * 2 + 1][3],
                             a[cur][mt][0], a[cur][mt][1], a[cur][mt][2], a[cur][mt][3],
                             rb[cur][ng][1], rb[cur][ng][3]);
                }
            }
        }
        cp_commit();   // close chunk c+1's group (empty on last iter; harmless)
    }

    // ---- epilogue: bias + store fp32 ----
    {
        const int r0 = m0 + wm * 64 + (lane >> 2);
        const int cbase = n0 + wn * 64 + (lane & 3) * 2;
        const float2* bp = reinterpret_cast<const float2*>(bias + cbase);
        float2 bv[8];
        #pragma unroll
        for (int nt = 0; nt < 8; ++nt) bv[nt] = bp[nt * 4];

        #pragma unroll
        for (int mt = 0; mt < 4; ++mt) {
            const size_t rowa = (size_t)(r0 + mt * 16) * N_DIM;
            const size_t rowb = rowa + 8 * N_DIM;
            #pragma unroll
            for (int nt = 0; nt < 8; ++nt) {
                const int col = cbase + nt * 8;
                float2 o0, o1;
                o0.x = acc[mt][nt][0] + bv[nt].x;
                o0.y = acc[mt][nt][1] + bv[nt].y;
                o1.x = acc[mt][nt][2] + bv[nt].x;
                o1.y = acc[mt][nt][3] + bv[nt].y;
                *reinterpret_cast<float2*>(out + rowa + col) = o0;
                *reinterpret_cast<float2*>(out + rowb + col) = o1;
            }
        }
    }
}

// ---------------- launch ----------------
extern "C" void kernel_launch(void* const* d_in, const int* in_sizes, int n_in,
                              void* d_out, int out_size) {
    (void)in_sizes; (void)n_in; (void)out_size;
    const float* x = (const float*)d_in[0];
    const float* w = (const float*)d_in[1];
    const float* bias = (const float*)d_in[2];
    float* out = (float*)d_out;

    static int once = []() {
        cudaFuncSetAttribute(gemm_kernel, cudaFuncAttributeMaxDynamicSharedMemorySize, SMEM_DYN);
        return 0;
    }();
    (void)once;

    // 1) fused prep: weight fake-quant -> fp16 AND x -> fp16
    prep_kernel<<<QUANT_BLOCKS + CVT_BLOCKS, 256>>>((const float4*)w, (const float4*)x);
    // 2) fp16 mma.sync GEMM + bias
    dim3 grid(N_DIM / BN, M_DIM / BM);
    gemm_kernel<<<grid, THREADS, SMEM_DYN>>>(bias, out);
}